// round 1
// baseline (speedup 1.0000x reference)
#include <cuda_runtime.h>
#include <stdint.h>

// YOLOv5 post-processing: conf+argmax -> top-1000 (stable desc) -> greedy NMS
// (class-offset trick) -> scale_coords. One block per image.
//
// Static problem constants (from reference):
#define NANCH   15120
#define NPAD    16384      // next pow2 for bitonic sort
#define KDET    1000
#define NB      128
#define NTHREADS 1024
#define CONF_THRES 0.25f
#define IOU_THRES  0.45f
#define MAX_WH     4096.0f
#define GAIN       0.5f
#define PAD_H      12.0f
#define LIM_W      1280.0f
#define LIM_H      720.0f

#define SMEM_BYTES (NPAD * 8)   // 131072

// Output layout (all float32, flattened + concatenated in reference return order):
//   boxes  [128,1000,4] : [0       .. 512000)
//   scores [128,1000]   : [512000  .. 640000)
//   labels [128,1000]   : [640000  .. 768000)
//   valid  [128,1000]   : [768000  .. 896000)
#define OFF_SCORES (NB * KDET * 4)
#define OFF_LABELS (OFF_SCORES + NB * KDET)
#define OFF_VALID  (OFF_LABELS + NB * KDET)

__global__ __launch_bounds__(NTHREADS, 1)
void yolo_nms_kernel(const float* __restrict__ pred, float* __restrict__ out)
{
    extern __shared__ unsigned char smem_raw[];
    unsigned long long* s = (unsigned long long*)smem_raw;

    const int b = blockIdx.x;
    const int t = threadIdx.x;
    const float* p = pred + (size_t)b * NANCH * 8;

    // ---------------- Phase A: confidence + key packing ----------------
    // key = (float_bits(conf) << 32) | (0xFFFFFFFF - i)   (conf >= 0 so bits
    // are order-preserving; low bits make sort stable with lowest-index-first
    // on ties, matching jax lax.top_k). We store ~key and sort ASCENDING so
    // element 0..K-1 of the sorted array are the top-K in descending order.
    for (int i = t; i < NPAD; i += NTHREADS) {
        unsigned long long key = 0ull;
        if (i < NANCH) {
            const float4 v1 = __ldg((const float4*)(p + (size_t)i * 8 + 4));
            const float obj = v1.x;
            const float m0 = obj * v1.y;
            const float m1 = obj * v1.z;
            const float m2 = obj * v1.w;
            float conf = m0;
            if (m1 > conf) conf = m1;
            if (m2 > conf) conf = m2;
            conf = (conf > CONF_THRES) ? conf : 0.0f;
            key = ((unsigned long long)__float_as_uint(conf) << 32)
                | (unsigned long long)(0xFFFFFFFFu - (unsigned)i);
        }
        s[i] = ~key;
    }
    __syncthreads();

    // ---------------- Phase B: bitonic sort (ascending on ~key) ---------
    for (int k = 2; k <= NPAD; k <<= 1) {
        for (int j = k >> 1; j > 0; j >>= 1) {
            for (int i = t; i < NPAD; i += NTHREADS) {
                const int ixj = i ^ j;
                if (ixj > i) {
                    const unsigned long long a = s[i];
                    const unsigned long long c = s[ixj];
                    const bool up = ((i & k) == 0);
                    if ((a > c) == up) { s[i] = c; s[ixj] = a; }
                }
            }
            __syncthreads();
        }
    }

    // ---------------- Phase C: gather top-K, build NMS arrays -----------
    unsigned long long mykey = 0ull;
    if (t < KDET) mykey = ~s[t];
    __syncthreads();   // all reads of s done; smem region is now reused

    float4* bo   = (float4*)(smem_raw);                 // offset boxes  [K]
    float4* ob   = (float4*)(smem_raw + 16384);         // orig boxes    [K]
    float*  area = (float*) (smem_raw + 32768);         // areas (offset)[K]
    float*  sc   = (float*) (smem_raw + 36864);         // scores        [K]
    int*    kp   = (int*)   (smem_raw + 40960);         // keep flags    [K]
    int*    cl   = (int*)   (smem_raw + 45056);         // class idx     [K]

    if (t < KDET) {
        const float score = __uint_as_float((unsigned)(mykey >> 32));
        const int idx = (int)(0xFFFFFFFFu - (unsigned)mykey);
        const float4 v0 = __ldg((const float4*)(p + (size_t)idx * 8));
        const float4 v1 = __ldg((const float4*)(p + (size_t)idx * 8 + 4));

        const float cx = v0.x, cy = v0.y, w = v0.z, h = v0.w;
        const float x1 = cx - w / 2.0f;
        const float y1 = cy - h / 2.0f;
        const float x2 = cx + w / 2.0f;
        const float y2 = cy + h / 2.0f;

        const float obj = v1.x;
        const float m0 = obj * v1.y;
        const float m1 = obj * v1.z;
        const float m2 = obj * v1.w;
        int cls = 0; float best = m0;
        if (m1 > best) { best = m1; cls = 1; }
        if (m2 > best) { best = m2; cls = 2; }

        const float off = (float)cls * MAX_WH;
        const float ox1 = x1 + off, oy1 = y1 + off, ox2 = x2 + off, oy2 = y2 + off;

        bo[t]   = make_float4(ox1, oy1, ox2, oy2);
        ob[t]   = make_float4(x1, y1, x2, y2);
        area[t] = (ox2 - ox1) * (oy2 - oy1);   // ref computes area on OFFSET boxes
        sc[t]   = score;
        kp[t]   = (score > 0.0f) ? 1 : 0;      // keep0 = scores > 0
        cl[t]   = cls;
    }
    __syncthreads();

    float4 myb = make_float4(0.f, 0.f, 0.f, 0.f);
    float  mya = 0.f;
    if (t < KDET) { myb = bo[t]; mya = area[t]; }

    // ---------------- Phase D: greedy NMS (sequential over i) -----------
    for (int i = 0; i < KDET; ++i) {
        __syncthreads();
        if (kp[i] == 0) continue;      // uniform branch (broadcast load)
        const float4 bi = bo[i];
        const float  ai = area[i];
        if (t > i && t < KDET) {
            const float lx = fmaxf(bi.x, myb.x);
            const float ly = fmaxf(bi.y, myb.y);
            const float rx = fminf(bi.z, myb.z);
            const float ry = fminf(bi.w, myb.w);
            const float ww = fmaxf(rx - lx, 0.0f);
            const float hh = fmaxf(ry - ly, 0.0f);
            const float inter = ww * hh;
            const float iou = inter / (ai + mya - inter + 1e-7f);
            if (iou > IOU_THRES) kp[t] = 0;
        }
    }
    __syncthreads();

    // ---------------- Phase E: scale_coords + outputs --------------------
    if (t < KDET) {
        const int   k  = kp[t];
        const float kf = k ? 1.0f : 0.0f;
        const float4 bx = ob[t];

        // (boxes - pad)/gain, clip [0, lim], round-half-even
        const float fx1 = rintf(fminf(fmaxf((bx.x - 0.0f) / GAIN, 0.0f), LIM_W));
        const float fy1 = rintf(fminf(fmaxf((bx.y - PAD_H) / GAIN, 0.0f), LIM_H));
        const float fx2 = rintf(fminf(fmaxf((bx.z - 0.0f) / GAIN, 0.0f), LIM_W));
        const float fy2 = rintf(fminf(fmaxf((bx.w - PAD_H) / GAIN, 0.0f), LIM_H));

        float* ob_out = out + (size_t)b * KDET * 4 + (size_t)t * 4;
        ob_out[0] = fx1 * kf;
        ob_out[1] = fy1 * kf;
        ob_out[2] = fx2 * kf;
        ob_out[3] = fy2 * kf;

        out[OFF_SCORES + b * KDET + t] = sc[t] * kf;
        out[OFF_LABELS + b * KDET + t] = (float)(k ? (cl[t] + 1) : 0);
        out[OFF_VALID  + b * KDET + t] = kf;
    }
}

extern "C" void kernel_launch(void* const* d_in, const int* in_sizes, int n_in,
                              void* d_out, int out_size)
{
    (void)in_sizes; (void)n_in; (void)out_size;
    const float* pred = (const float*)d_in[0];
    float* out = (float*)d_out;

    cudaFuncSetAttribute(yolo_nms_kernel,
                         cudaFuncAttributeMaxDynamicSharedMemorySize, SMEM_BYTES);
    yolo_nms_kernel<<<NB, NTHREADS, SMEM_BYTES>>>(pred, out);
}

// round 2
// speedup vs baseline: 1.7326x; 1.7326x over previous
#include <cuda_runtime.h>
#include <stdint.h>

// YOLOv5 post-processing, v2:
//   conf+argmax -> 64-bit radix-select top-1000 -> small bitonic sort ->
//   class partition (packed scan) -> chunked per-class bitmask NMS -> scale_coords.
// One block (1024 threads) per image.

#define NANCH    15120
#define KDET     1000
#define NB       128
#define NT       1024
#define CONF_THRES 0.25f
#define IOU_THRES  0.45f
#define MAX_WH     4096.0f
#define GAIN       0.5f
#define PAD_H      12.0f
#define LIM_W      1280.0f
#define LIM_H      720.0f

// Output layout (float32): boxes[128,1000,4] | scores[128,1000] | labels | valid
#define OFF_SCORES (NB * KDET * 4)
#define OFF_LABELS (OFF_SCORES + NB * KDET)
#define OFF_VALID  (OFF_LABELS + NB * KDET)

// ---- shared memory layout ----
// Phase A/B (select):
#define SM_KEYS    0                 // u64[15120] = 120960 B
#define SM_KEYBUF  120960            // u64[1024]  -> 129152
#define SM_HIST    129152            // u32[256]   -> 130176
#define SM_CTRL    130176            // prefix(u64), rank(i32), cnt(i32) -> 130240
#define SMEM_BYTES 130304
// Overlay on top of SM_KEYS after selection is done:
#define SM_GBOX    0                 // float4[1024] offset boxes (grouped) 16384
#define SM_GAR     16384             // float[1024] areas          -> 20480
#define SM_SCAN    20480             // u64[1024] packed scan      -> 28672
#define SM_ALIVEB  28672             // u32[1024] final alive      -> 32768
#define SM_GBASE   32768             // u32[1024] class base       -> 36864
#define SM_ALIVEW  36864             // u32[32] per-chunk alive    -> 36992

__global__ __launch_bounds__(NT, 1)
void yolo_nms_kernel(const float* __restrict__ pred, float* __restrict__ out)
{
    extern __shared__ unsigned char smem[];
    unsigned long long* keys   = (unsigned long long*)(smem + SM_KEYS);
    unsigned long long* keybuf = (unsigned long long*)(smem + SM_KEYBUF);
    unsigned int*       hist   = (unsigned int*)      (smem + SM_HIST);
    unsigned long long* sPrefix= (unsigned long long*)(smem + SM_CTRL);
    int*                sRank  = (int*)               (smem + SM_CTRL + 8);
    int*                sCnt   = (int*)               (smem + SM_CTRL + 12);

    const int b = blockIdx.x;
    const int t = threadIdx.x;
    const float* p = pred + (size_t)b * NANCH * 8;

    // ---------------- Phase A: confidence -> 64-bit keys ----------------
    // key = conf_bits<<32 | (0xFFFFFFFF - i): desc conf, asc index on ties.
    for (int i = t; i < NANCH; i += NT) {
        const float4 v1 = __ldg((const float4*)(p + (size_t)i * 8 + 4));
        const float obj = v1.x;
        float conf = obj * v1.y;
        const float m1 = obj * v1.z;
        const float m2 = obj * v1.w;
        if (m1 > conf) conf = m1;
        if (m2 > conf) conf = m2;
        conf = (conf > CONF_THRES) ? conf : 0.0f;
        keys[i] = ((unsigned long long)__float_as_uint(conf) << 32)
                | (unsigned long long)(0xFFFFFFFFu - (unsigned)i);
    }

    // ---------------- Phase B: 64-bit radix select (rank 1000) ----------
    unsigned long long prefix = 0ull;
    int rank = KDET;
    for (int shift = 56; shift >= 0; shift -= 8) {
        if (t < 256) hist[t] = 0u;
        __syncthreads();
        const unsigned long long pm =
            (shift == 56) ? 0ull : ~((1ull << (shift + 8)) - 1ull);
        for (int i = t; i < NANCH; i += NT) {
            const unsigned long long key = keys[i];
            if ((key & pm) == prefix)
                atomicAdd(&hist[(unsigned)(key >> shift) & 255u], 1u);
        }
        __syncthreads();
        if (t == 0) {
            int acc = 0, sel = 0, nr = rank;
            for (int v = 255; v >= 0; --v) {
                const int h = (int)hist[v];
                if (acc + h >= rank) { sel = v; nr = rank - acc; break; }
                acc += h;
            }
            *sPrefix = prefix | ((unsigned long long)sel << shift);
            *sRank = nr;
            *sCnt = 0;
        }
        __syncthreads();
        prefix = *sPrefix;
        rank = *sRank;
    }
    // prefix == exact value of the 1000th-largest key; keys distinct.

    // ---------------- Compaction: gather the 1000 keys >= prefix --------
    for (int i = t; i < NANCH; i += NT) {
        const unsigned long long key = keys[i];
        if (key >= prefix) {
            const int pos = atomicAdd(sCnt, 1);
            keybuf[pos] = key;
        }
    }
    if (t >= KDET) keybuf[t] = 0ull;   // padding sorts last
    __syncthreads();

    // ---------------- Small bitonic sort (1024 keys, descending) --------
    for (int k = 2; k <= NT; k <<= 1) {
        for (int j = k >> 1; j > 0; j >>= 1) {
            const int ixj = t ^ j;
            if (ixj > t) {
                const unsigned long long a = keybuf[t];
                const unsigned long long c = keybuf[ixj];
                const bool desc = ((t & k) == 0);
                if ((a < c) == desc) { keybuf[t] = c; keybuf[ixj] = a; }
            }
            __syncthreads();
        }
    }

    // ---------------- Phase C: decode top-K, class partition ------------
    const unsigned long long mykey = keybuf[t];
    const float score = __uint_as_float((unsigned)(mykey >> 32));
    float x1 = 0.f, y1 = 0.f, x2 = 0.f, y2 = 0.f;
    float ox1 = 0.f, oy1 = 0.f, ox2 = 0.f, oy2 = 0.f, ar = 0.f;
    int cls = 0;
    if (t < KDET) {
        const int idx = (int)(0xFFFFFFFFu - (unsigned)mykey);
        const float4 v0 = __ldg((const float4*)(p + (size_t)idx * 8));
        const float4 v1 = __ldg((const float4*)(p + (size_t)idx * 8 + 4));
        const float cx = v0.x, cy = v0.y, w = v0.z, h = v0.w;
        x1 = cx - w / 2.0f; y1 = cy - h / 2.0f;
        x2 = cx + w / 2.0f; y2 = cy + h / 2.0f;
        const float obj = v1.x;
        const float m0 = obj * v1.y, m1 = obj * v1.z, m2 = obj * v1.w;
        float best = m0; cls = 0;
        if (m1 > best) { best = m1; cls = 1; }
        if (m2 > best) { best = m2; cls = 2; }
        const float off = (float)cls * MAX_WH;
        ox1 = x1 + off; oy1 = y1 + off; ox2 = x2 + off; oy2 = y2 + off;
        ar = (ox2 - ox1) * (oy2 - oy1);   // ref: area on OFFSET boxes
    }
    // partition class: real alive items keep cls in {0,1,2}; dead -> 3
    const int pcls = (t < KDET && score > 0.0f) ? cls : 3;

    // packed inclusive scan over 4x16-bit counters (overlay region is free:
    // keys[] no longer needed — keybuf/hist live outside the overlay)
    unsigned long long* scanb = (unsigned long long*)(smem + SM_SCAN);
    float4* gbox = (float4*)(smem + SM_GBOX);
    float*  garA = (float*) (smem + SM_GAR);
    unsigned int* aliveB = (unsigned int*)(smem + SM_ALIVEB);
    unsigned int* gbase  = (unsigned int*)(smem + SM_GBASE);
    unsigned int* aliveW = (unsigned int*)(smem + SM_ALIVEW);

    const unsigned long long myval = 1ull << (16 * pcls);
    __syncthreads();          // bitonic reads done before overlay writes? keybuf untouched; scan region overlays keys only — safe
    scanb[t] = myval;
    __syncthreads();
    #pragma unroll
    for (int d = 1; d < NT; d <<= 1) {
        const unsigned long long add = (t >= d) ? scanb[t - d] : 0ull;
        __syncthreads();
        scanb[t] += add;
        __syncthreads();
    }
    const unsigned long long incl = scanb[t];
    const unsigned long long tot  = scanb[NT - 1];
    const unsigned long long excl = incl - myval;
    const unsigned c0 = (unsigned)(tot       & 0xFFFF);
    const unsigned c1 = (unsigned)((tot>>16) & 0xFFFF);
    const unsigned c2 = (unsigned)((tot>>32) & 0xFFFF);
    const unsigned baseArr4[4] = {0u, c0, c0 + c1, c0 + c1 + c2};
    const unsigned mybase = baseArr4[pcls];
    const unsigned myrank = (unsigned)(excl >> (16 * pcls)) & 0xFFFFu;
    const unsigned mypos  = mybase + myrank;
    const unsigned base3  = c0 + c1 + c2;   // dead region start

    __syncthreads();   // scan reads done before overlay re-writes
    gbox[mypos] = make_float4(ox1, oy1, ox2, oy2);
    garA[mypos] = ar;
    gbase[mypos] = mybase;
    __syncthreads();

    // ---------------- Phase D: chunked bitmask NMS (grouped order) ------
    // Thread identity switches to grouped position pp = threadIdx.x.
    const int pp = t;
    const float4 mb = gbox[pp];
    const float  ma = garA[pp];
    const int    blo = (int)gbase[pp];
    bool my_dead = (pp >= (int)base3);
    const int mywarp = t >> 5;

    for (int k = 0; k < 32; ++k) {
        // suppression mask: which members of chunk k would kill pp (if alive)
        const int qlo = max(k << 5, blo);
        const int qhi = min((k << 5) + 32, pp);
        unsigned mask = 0u;
        for (int q = qlo; q < qhi; ++q) {
            const float4 qb = gbox[q];
            const float lx = fmaxf(qb.x, mb.x);
            const float ly = fmaxf(qb.y, mb.y);
            const float rx = fminf(qb.z, mb.z);
            const float ry = fminf(qb.w, mb.w);
            const float ww = fmaxf(rx - lx, 0.0f);
            const float hh = fmaxf(ry - ly, 0.0f);
            const float inter = ww * hh;
            const float iou = inter / (garA[q] + ma - inter + 1e-7f);
            if (iou > IOU_THRES) mask |= 1u << (q - (k << 5));
        }
        // chunk k == warp k resolves its own internal order
        if (mywarp == k) {
            const int m = t & 31;
            bool aliveL = !my_dead;
            #pragma unroll 1
            for (int q = 0; q < 32; ++q) {
                const unsigned aw = __ballot_sync(0xFFFFFFFFu, aliveL);
                if (((aw >> q) & 1u) && (m > q) && ((mask >> q) & 1u))
                    aliveL = false;
            }
            const unsigned awf = __ballot_sync(0xFFFFFFFFu, aliveL);
            if ((t & 31) == 0) aliveW[k] = awf;
            my_dead = !aliveL;
        }
        __syncthreads();
        const unsigned aw = aliveW[k];
        if (mask & aw) my_dead = true;
    }
    aliveB[pp] = my_dead ? 0u : 1u;
    __syncthreads();

    // ---------------- Phase E: scale_coords + outputs --------------------
    if (t < KDET) {
        const int kkeep = (int)aliveB[mypos];
        const float kf = kkeep ? 1.0f : 0.0f;

        const float fx1 = rintf(fminf(fmaxf((x1 - 0.0f) / GAIN, 0.0f), LIM_W));
        const float fy1 = rintf(fminf(fmaxf((y1 - PAD_H) / GAIN, 0.0f), LIM_H));
        const float fx2 = rintf(fminf(fmaxf((x2 - 0.0f) / GAIN, 0.0f), LIM_W));
        const float fy2 = rintf(fminf(fmaxf((y2 - PAD_H) / GAIN, 0.0f), LIM_H));

        float* ob_out = out + (size_t)b * KDET * 4 + (size_t)t * 4;
        ob_out[0] = fx1 * kf;
        ob_out[1] = fy1 * kf;
        ob_out[2] = fx2 * kf;
        ob_out[3] = fy2 * kf;

        out[OFF_SCORES + b * KDET + t] = score * kf;
        out[OFF_LABELS + b * KDET + t] = (float)(kkeep ? (cls + 1) : 0);
        out[OFF_VALID  + b * KDET + t] = kf;
    }
}

extern "C" void kernel_launch(void* const* d_in, const int* in_sizes, int n_in,
                              void* d_out, int out_size)
{
    (void)in_sizes; (void)n_in; (void)out_size;
    const float* pred = (const float*)d_in[0];
    float* out = (float*)d_out;

    cudaFuncSetAttribute(yolo_nms_kernel,
                         cudaFuncAttributeMaxDynamicSharedMemorySize, SMEM_BYTES);
    yolo_nms_kernel<<<NB, NT, SMEM_BYTES>>>(pred, out);
}

// round 3
// speedup vs baseline: 2.1814x; 1.2591x over previous
#include <cuda_runtime.h>
#include <stdint.h>

// YOLOv5 post-processing v3:
//   histogram(4096-bin) top-1000 select -> hybrid shfl/smem bitonic sort ->
//   class partition (shfl scan) -> pipelined chunked bitmask NMS -> scale_coords.
// One block (1024 threads) per image.

#define NANCH    15120
#define KDET     1000
#define NB       128
#define NT       1024
#define NITER    15          // ceil(15120/1024)
#define FULLM    0xFFFFFFFFu
#define CONF_THRES 0.25f
#define IOU_THRES  0.45f
#define MAX_WH     4096.0f
#define GAIN       0.5f
#define PAD_H      12.0f
#define LIM_W      1280.0f
#define LIM_H      720.0f

// Output layout (float32): boxes[128,1000,4] | scores[128,1000] | labels | valid
#define OFF_SCORES (NB * KDET * 4)
#define OFF_LABELS (OFF_SCORES + NB * KDET)
#define OFF_VALID  (OFF_LABELS + NB * KDET)

struct SmemT {
    union {
        unsigned int       hist[4096];       // phase A histogram (16 KB)
        unsigned long long binbuf[2048];     // boundary-bin keys  (16 KB)
        float4             gbox[1024];       // NMS grouped boxes  (16 KB)
    } u0;
    union {
        unsigned long long keybuf[1024];     // selected keys / sort buffer (8 KB)
        struct { float garA[1024]; unsigned int gbase[1024]; } n; // NMS (8 KB)
    } u1;
    unsigned short digitS[NANCH];            // digit+1 per anchor, 0 = not cand (30240 B)
    unsigned int aliveB[1024];
    unsigned long long wsum[32];
    unsigned int aliveW[32];
    int sCut;
    int cntA;
    int cntB;
};

__device__ __forceinline__ unsigned long long bitonic_shfl_step(
    unsigned long long v, int j, int k, int t)
{
    unsigned long long pv = __shfl_xor_sync(FULLM, v, j);
    const bool desc  = ((t & k) == 0);
    const bool lower = ((t & j) == 0);
    const bool keepmax = (lower == desc);
    const unsigned long long mx = (v > pv) ? v : pv;
    const unsigned long long mn = (v > pv) ? pv : v;
    return keepmax ? mx : mn;
}

__device__ __forceinline__ unsigned chunk_mask(
    int k, int pp, int blo, float4 mb, float ma,
    const float4* __restrict__ gbox, const float* __restrict__ garA)
{
    const int qbase = k << 5;
    const int qlo = max(qbase, blo);
    const int qhi = min(qbase + 32, pp);
    unsigned mask = 0u;
    #pragma unroll 4
    for (int q = qlo; q < qhi; ++q) {
        const float4 qb = gbox[q];
        const float lx = fmaxf(qb.x, mb.x);
        const float ly = fmaxf(qb.y, mb.y);
        const float rx = fminf(qb.z, mb.z);
        const float ry = fminf(qb.w, mb.w);
        const float ww = fmaxf(rx - lx, 0.0f);
        const float hh = fmaxf(ry - ly, 0.0f);
        const float inter = ww * hh;
        const float iou = inter / (garA[q] + ma - inter + 1e-7f);
        if (iou > IOU_THRES) mask |= 1u << (q - qbase);
    }
    return mask;
}

__global__ __launch_bounds__(NT, 1)
void yolo_nms_kernel(const float* __restrict__ pred, float* __restrict__ out)
{
    extern __shared__ unsigned char smem_raw[];
    SmemT* sm = (SmemT*)smem_raw;

    const int b = blockIdx.x;
    const int t = threadIdx.x;
    const int lane = t & 31;
    const int w = t >> 5;
    const unsigned lanemask_lt = (1u << lane) - 1u;
    const float* p = pred + (size_t)b * NANCH * 8;

    // ---------------- init ----------------
    #pragma unroll
    for (int j = 0; j < 4; ++j) sm->u0.hist[t + j * NT] = 0u;
    if (t == 0) { sm->sCut = 0; sm->cntA = 0; sm->cntB = 0; }
    __syncthreads();

    // ---------------- Phase A: conf -> digit histogram ----------------
    #pragma unroll
    for (int j = 0; j < NITER; ++j) {
        const int i = t + j * NT;
        if (i < NANCH) {
            const float4 v1 = __ldg((const float4*)(p + (size_t)i * 8 + 4));
            const float obj = v1.x;
            float conf = obj * v1.y;
            const float m1 = obj * v1.z;
            const float m2 = obj * v1.w;
            if (m1 > conf) conf = m1;
            if (m2 > conf) conf = m2;
            unsigned short sd = 0;
            if (conf > CONF_THRES) {
                unsigned d = (__float_as_uint(conf) >> 12) - 0x3E800u;
                if (d > 4095u) d = 4095u;
                atomicAdd(&sm->u0.hist[d], 1u);
                sd = (unsigned short)(d + 1u);
            }
            sm->digitS[i] = sd;
        }
    }
    __syncthreads();

    // ---------------- find cutoff bin (suffix scan from top) ----------
    // thread t owns bins [4t, 4t+4)
    unsigned h0 = sm->u0.hist[4 * t + 0];
    unsigned h1 = sm->u0.hist[4 * t + 1];
    unsigned h2 = sm->u0.hist[4 * t + 2];
    unsigned h3 = sm->u0.hist[4 * t + 3];
    const unsigned st = h0 + h1 + h2 + h3;
    // suffix-inclusive within warp (sum over lanes >= lane)
    unsigned long long sv = st;
    #pragma unroll
    for (int d = 1; d < 32; d <<= 1) {
        unsigned long long tmp = __shfl_down_sync(FULLM, sv, d);
        if (lane + d < 32) sv += tmp;
    }
    if (lane == 0) sm->wsum[w] = sv;   // warp total (sum over all its lanes)
    __syncthreads();
    if (w == 0) {
        unsigned long long x = sm->wsum[lane];
        unsigned long long own = x;
        #pragma unroll
        for (int d = 1; d < 32; d <<= 1) {
            unsigned long long tmp = __shfl_down_sync(FULLM, x, d);
            if (lane + d < 32) x += tmp;
        }
        sm->wsum[lane] = x - own;      // suffix-EXCLUSIVE over warps (> w)
    }
    __syncthreads();
    {
        const unsigned long long sufThread =
            sm->wsum[w] + (unsigned long long)(sv - st);  // count over threads > t
        if (sufThread < (unsigned long long)KDET &&
            sufThread + st >= (unsigned long long)KDET) {
            unsigned run = (unsigned)sufThread;
            int cut = 4 * t;
            run += h3; if (run >= KDET) cut = 4 * t + 3;
            else { run += h2; if (run >= KDET) cut = 4 * t + 2;
            else { run += h1; if (run >= KDET) cut = 4 * t + 1;
            else { cut = 4 * t; } } }
            sm->sCut = cut;
        }
    }
    __syncthreads();
    const unsigned cutp1 = (unsigned)sm->sCut + 1u;
    __syncthreads();   // hist reads done; u0 region becomes binbuf

    // ---------------- collect: strict set + boundary bin --------------
    #pragma unroll
    for (int j = 0; j < NITER; ++j) {
        const int i = t + j * NT;
        unsigned sd = 0;
        if (i < NANCH) sd = sm->digitS[i];
        const bool isA = sd > cutp1;
        const bool isB = sd == cutp1;
        const unsigned mA = __ballot_sync(FULLM, isA);
        const unsigned mB = __ballot_sync(FULLM, isB);
        int posA = 0, posB = 0;
        if (mA) {
            const int ldr = __ffs(mA) - 1;
            int base_;
            if (lane == ldr) base_ = atomicAdd(&sm->cntA, __popc(mA));
            base_ = __shfl_sync(FULLM, base_, ldr);
            posA = base_ + __popc(mA & lanemask_lt);
        }
        if (mB) {
            const int ldr = __ffs(mB) - 1;
            int base_;
            if (lane == ldr) base_ = atomicAdd(&sm->cntB, __popc(mB));
            base_ = __shfl_sync(FULLM, base_, ldr);
            posB = base_ + __popc(mB & lanemask_lt);
        }
        if (isA || isB) {
            const float4 v1 = __ldg((const float4*)(p + (size_t)i * 8 + 4));
            const float obj = v1.x;
            float conf = obj * v1.y;
            const float m1 = obj * v1.z;
            const float m2 = obj * v1.w;
            if (m1 > conf) conf = m1;
            if (m2 > conf) conf = m2;
            const unsigned long long key =
                ((unsigned long long)__float_as_uint(conf) << 32)
                | (unsigned long long)(0xFFFFFFFFu - (unsigned)i);
            if (isA) { if (posA < 1024) sm->u1.keybuf[posA] = key; }
            else     { if (posB < 2048) sm->u0.binbuf[posB] = key; }
        }
    }
    __syncthreads();

    const int C = min(sm->cntA, 1024);
    const int m = min(sm->cntB, 2048);
    const int need = max(0, min(KDET - C, m));

    // exact rank within boundary bin (keys distinct: index bits)
    for (int i = t; i < m; i += NT) {
        const unsigned long long mykey = sm->u0.binbuf[i];
        int rank = 0;
        for (int q = 0; q < m; ++q)
            rank += (sm->u0.binbuf[q] > mykey) ? 1 : 0;
        if (rank < need) sm->u1.keybuf[C + rank] = mykey;
    }
    if (t >= C + need) sm->u1.keybuf[t] = 0ull;   // pad
    __syncthreads();

    // ---------------- bitonic sort 1024 desc (hybrid shfl/smem) -------
    unsigned long long v = sm->u1.keybuf[t];
    #pragma unroll
    for (int k = 2; k <= 32; k <<= 1)
        for (int j = k >> 1; j >= 1; j >>= 1)
            v = bitonic_shfl_step(v, j, k, t);
    for (int k = 64; k <= NT; k <<= 1) {
        for (int j = k >> 1; j >= 32; j >>= 1) {
            __syncthreads();
            sm->u1.keybuf[t] = v;
            __syncthreads();
            const unsigned long long pv = sm->u1.keybuf[t ^ j];
            const bool desc  = ((t & k) == 0);
            const bool lower = ((t & j) == 0);
            const bool keepmax = (lower == desc);
            const unsigned long long mx = (v > pv) ? v : pv;
            const unsigned long long mn = (v > pv) ? pv : v;
            v = keepmax ? mx : mn;
        }
        #pragma unroll
        for (int j = 16; j >= 1; j >>= 1)
            v = bitonic_shfl_step(v, j, k, t);
    }
    // v = sorted element t (descending); keybuf no longer needed.

    // ---------------- decode + class partition ------------------------
    const float score = __uint_as_float((unsigned)(v >> 32));
    float x1 = 0.f, y1 = 0.f, x2 = 0.f, y2 = 0.f;
    float ox1 = 0.f, oy1 = 0.f, ox2 = 0.f, oy2 = 0.f, ar = 0.f;
    int cls = 0;
    if (t < KDET && score > 0.0f) {
        const int idx = (int)(0xFFFFFFFFu - (unsigned)v);
        const float4 v0 = __ldg((const float4*)(p + (size_t)idx * 8));
        const float4 v1 = __ldg((const float4*)(p + (size_t)idx * 8 + 4));
        const float cx = v0.x, cy = v0.y, ww = v0.z, hh = v0.w;
        x1 = cx - ww / 2.0f; y1 = cy - hh / 2.0f;
        x2 = cx + ww / 2.0f; y2 = cy + hh / 2.0f;
        const float obj = v1.x;
        const float m0 = obj * v1.y, mm1 = obj * v1.z, mm2 = obj * v1.w;
        float best = m0; cls = 0;
        if (mm1 > best) { best = mm1; cls = 1; }
        if (mm2 > best) { best = mm2; cls = 2; }
        const float off = (float)cls * MAX_WH;
        ox1 = x1 + off; oy1 = y1 + off; ox2 = x2 + off; oy2 = y2 + off;
        ar = (ox2 - ox1) * (oy2 - oy1);   // ref: area on OFFSET boxes
    }
    const int pcls = (t < KDET && score > 0.0f) ? cls : 3;

    // packed 4x16-bit counter scan via shfl
    const unsigned long long myval = 1ull << (16 * pcls);
    unsigned long long x = myval;
    #pragma unroll
    for (int d = 1; d < 32; d <<= 1) {
        const unsigned long long y = __shfl_up_sync(FULLM, x, d);
        if (lane >= d) x += y;
    }
    __syncthreads();   // (protect wsum reuse)
    if (lane == 31) sm->wsum[w] = x;
    __syncthreads();
    if (w == 0) {
        unsigned long long z = sm->wsum[lane];
        #pragma unroll
        for (int d = 1; d < 32; d <<= 1) {
            const unsigned long long y = __shfl_up_sync(FULLM, z, d);
            if (lane >= d) z += y;
        }
        sm->wsum[lane] = z;
    }
    __syncthreads();
    const unsigned long long base = (w > 0) ? sm->wsum[w - 1] : 0ull;
    const unsigned long long incl = base + x;
    const unsigned long long tot  = sm->wsum[31];
    const unsigned long long excl = incl - myval;
    const unsigned c0 = (unsigned)(tot & 0xFFFF);
    const unsigned c1 = (unsigned)((tot >> 16) & 0xFFFF);
    const unsigned c2 = (unsigned)((tot >> 32) & 0xFFFF);
    const unsigned baseArr[4] = {0u, c0, c0 + c1, c0 + c1 + c2};
    const unsigned mybase = baseArr[pcls];
    const unsigned myrank = (unsigned)(excl >> (16 * pcls)) & 0xFFFFu;
    const unsigned mypos  = mybase + myrank;
    const unsigned base3  = c0 + c1 + c2;

    __syncthreads();   // u0/u1 switch to NMS arrays
    sm->u0.gbox[mypos]   = make_float4(ox1, oy1, ox2, oy2);
    sm->u1.n.garA[mypos] = ar;
    sm->u1.n.gbase[mypos]= mybase;
    __syncthreads();

    // ---------------- pipelined chunked bitmask NMS --------------------
    const int pp = t;
    const float4 mb = sm->u0.gbox[pp];
    const float  ma = sm->u1.n.garA[pp];
    const int    blo = (int)sm->u1.n.gbase[pp];
    bool my_dead = (pp >= (int)base3);

    unsigned mcur = chunk_mask(0, pp, blo, mb, ma, sm->u0.gbox, sm->u1.n.garA);
    for (int k = 0; k < 32; ++k) {
        unsigned mnext = 0u;
        if (w == k) {
            // resolve internal order of chunk k (serial ballot chain)
            bool aliveL = !my_dead;
            #pragma unroll
            for (int q = 0; q < 32; ++q) {
                const unsigned aw = __ballot_sync(FULLM, aliveL);
                if (((aw >> q) & 1u) && lane > q && ((mcur >> q) & 1u))
                    aliveL = false;
            }
            const unsigned awf = __ballot_sync(FULLM, aliveL);
            if (lane == 0) sm->aliveW[k] = awf;
            my_dead = !aliveL;
        } else if (k < 31) {
            mnext = chunk_mask(k + 1, pp, blo, mb, ma, sm->u0.gbox, sm->u1.n.garA);
        }
        __syncthreads();
        if (w > k) {
            const unsigned aw = sm->aliveW[k];
            if (mcur & aw) my_dead = true;
        }
        mcur = mnext;
    }
    sm->aliveB[pp] = my_dead ? 0u : 1u;
    __syncthreads();

    // ---------------- scale_coords + outputs ---------------------------
    if (t < KDET) {
        const int kkeep = (int)sm->aliveB[mypos];
        const float kf = kkeep ? 1.0f : 0.0f;

        const float fx1 = rintf(fminf(fmaxf((x1 - 0.0f) / GAIN, 0.0f), LIM_W));
        const float fy1 = rintf(fminf(fmaxf((y1 - PAD_H) / GAIN, 0.0f), LIM_H));
        const float fx2 = rintf(fminf(fmaxf((x2 - 0.0f) / GAIN, 0.0f), LIM_W));
        const float fy2 = rintf(fminf(fmaxf((y2 - PAD_H) / GAIN, 0.0f), LIM_H));

        ((float4*)out)[b * KDET + t] = make_float4(fx1 * kf, fy1 * kf, fx2 * kf, fy2 * kf);
        out[OFF_SCORES + b * KDET + t] = score * kf;
        out[OFF_LABELS + b * KDET + t] = (float)(kkeep ? (cls + 1) : 0);
        out[OFF_VALID  + b * KDET + t] = kf;
    }
}

extern "C" void kernel_launch(void* const* d_in, const int* in_sizes, int n_in,
                              void* d_out, int out_size)
{
    (void)in_sizes; (void)n_in; (void)out_size;
    const float* pred = (const float*)d_in[0];
    float* out = (float*)d_out;

    cudaFuncSetAttribute(yolo_nms_kernel,
                         cudaFuncAttributeMaxDynamicSharedMemorySize,
                         (int)sizeof(SmemT));
    yolo_nms_kernel<<<NB, NT, sizeof(SmemT)>>>(pred, out);
}